// round 1
// baseline (speedup 1.0000x reference)
#include <cuda_runtime.h>
#include <math.h>

typedef unsigned long long ull;

#define HEADS   8
#define DHQK    32
#define DHV     32
#define BSZ     8
#define HALO    3
#define WIN     14
#define WIN2    196          // 14*14
#define NPAD    224          // WIN2 padded to 7*32
#define QKVW    768          // 256 q + 512 kv channels per pixel
#define NPIX    4096         // 64*64
#define NBATCH  16
#define SCALE_QK 0.17677669529663687f   // 1/sqrt(32)

// Scratch: fused qkv per pixel, layout [b][pix][768]:
//   [0,256)   q   : channel = head*32 + d
//   [256,768) kv  : channel = head*64 + d (k: d<32, v: d>=32)  -- matches reference reshape
__device__ float g_qkv[(size_t)NBATCH * NPIX * QKVW];

// ---------- packed f32x2 helpers ----------
__device__ __forceinline__ ull pk2(float lo, float hi) {
    ull r; asm("mov.b64 %0, {%1, %2};" : "=l"(r) : "f"(lo), "f"(hi)); return r;
}
__device__ __forceinline__ ull fma2(ull a, ull b, ull c) {
    ull d; asm("fma.rn.f32x2 %0, %1, %2, %3;" : "=l"(d) : "l"(a), "l"(b), "l"(c)); return d;
}
__device__ __forceinline__ float2 upk2(ull v) {
    float2 r; asm("mov.b64 {%0, %1}, %2;" : "=f"(r.x), "=f"(r.y) : "l"(v)); return r;
}

// =====================================================================
// Kernel 1: fused QKV projection GEMM
//   out[m][n] = sum_c x[b][c][pix] * W[n][c]
//   M = 65536 (pixels), N = 768 (Wq rows 0..255, Wkv rows 256..767), K = 256
//   Block tile 128(M) x 128(N), 256 threads, thread tile 8x8, K-chunk 16.
//   f32x2 packed FMA in the inner loop (2x fp32 throughput on B300).
// =====================================================================
__global__ __launch_bounds__(256) void qkv_gemm(const float* __restrict__ x,
                                                const float* __restrict__ Wq,
                                                const float* __restrict__ Wkv) {
    __shared__ float As[16 * 128];   // [kk][m]
    __shared__ float Bs[16 * 132];   // [kk][n], padded row stride 132

    const int n0   = blockIdx.x * 128;            // 0..640 (never straddles 256 boundary)
    const int mblk = blockIdx.y;                  // 0..511
    const int b    = mblk >> 5;                   // 32 m-tiles per batch image
    const int pix0 = (mblk & 31) << 7;            // *128, two full image rows

    const float* xb = x + ((size_t)b * 256) * NPIX + pix0;
    const float* Wb = (n0 < 256) ? (Wq + (size_t)n0 * 256)
                                 : (Wkv + (size_t)(n0 - 256) * 256);

    const int tid = threadIdx.x;
    const int tmg = tid >> 4;        // 0..15 -> m rows tmg*8..tmg*8+7
    const int tng = tid & 15;        // 0..15 -> n cols tng*8..tng*8+7

    // load-index precompute
    const int la_c  = tid >> 5;           // 0..7
    const int la_m4 = (tid & 31) << 2;    // 0..124
    const int lb_o  = tid >> 1;           // 0..127
    const int lb_k8 = (tid & 1) << 3;     // 0 or 8

    ull acc[8][4];
    #pragma unroll
    for (int i = 0; i < 8; ++i)
        #pragma unroll
        for (int j = 0; j < 4; ++j) acc[i][j] = 0ull;

    for (int kc = 0; kc < 256; kc += 16) {
        // stage A (x): 16 c-rows x 128 pixels, fully coalesced 512B bursts
        #pragma unroll
        for (int i = 0; i < 2; ++i) {
            int c = la_c + i * 8;
            float4 v = *(const float4*)(xb + (size_t)(kc + c) * NPIX + la_m4);
            *(float4*)(As + c * 128 + la_m4) = v;
        }
        // stage B (W): 128 n-rows x 16 c, transpose into smem
        #pragma unroll
        for (int i = 0; i < 2; ++i) {
            float4 wv = *(const float4*)(Wb + (size_t)lb_o * 256 + kc + lb_k8 + i * 4);
            Bs[(lb_k8 + i * 4 + 0) * 132 + lb_o] = wv.x;
            Bs[(lb_k8 + i * 4 + 1) * 132 + lb_o] = wv.y;
            Bs[(lb_k8 + i * 4 + 2) * 132 + lb_o] = wv.z;
            Bs[(lb_k8 + i * 4 + 3) * 132 + lb_o] = wv.w;
        }
        __syncthreads();

        #pragma unroll
        for (int kk = 0; kk < 16; ++kk) {
            float4 a0 = *(const float4*)(As + kk * 128 + tmg * 8);
            float4 a1 = *(const float4*)(As + kk * 128 + tmg * 8 + 4);
            float4 b0 = *(const float4*)(Bs + kk * 132 + tng * 8);
            float4 b1 = *(const float4*)(Bs + kk * 132 + tng * 8 + 4);
            ull bp0 = pk2(b0.x, b0.y), bp1 = pk2(b0.z, b0.w);
            ull bp2 = pk2(b1.x, b1.y), bp3 = pk2(b1.z, b1.w);
            float av[8] = {a0.x, a0.y, a0.z, a0.w, a1.x, a1.y, a1.z, a1.w};
            #pragma unroll
            for (int i = 0; i < 8; ++i) {
                ull ad = pk2(av[i], av[i]);
                acc[i][0] = fma2(ad, bp0, acc[i][0]);
                acc[i][1] = fma2(ad, bp1, acc[i][1]);
                acc[i][2] = fma2(ad, bp2, acc[i][2]);
                acc[i][3] = fma2(ad, bp3, acc[i][3]);
            }
        }
        __syncthreads();
    }

    const size_t mbase = (size_t)b * NPIX + pix0;
    #pragma unroll
    for (int i = 0; i < 8; ++i) {
        int m = tmg * 8 + i;
        float2 p0 = upk2(acc[i][0]), p1 = upk2(acc[i][1]);
        float2 p2 = upk2(acc[i][2]), p3 = upk2(acc[i][3]);
        float* op = g_qkv + (mbase + m) * QKVW + n0 + tng * 8;
        *(float4*)(op)     = make_float4(p0.x, p0.y, p1.x, p1.y);
        *(float4*)(op + 4) = make_float4(p2.x, p2.y, p3.x, p3.y);
    }
}

// =====================================================================
// Kernel 2: halo block attention
//   grid = (64 blocks, 8 heads, 16 batch); 256 threads (8 warps).
//   Warp w owns query rows w*8..w*8+7; lane owns key-cols {l, l+32, ... } (7),
//   and in the PV phase lane == output dim d.
//   K/V stored transposed in smem stride 225 (conflict-free both phases).
//   Zero-padded halo keys participate in softmax with logit = pos_bias (k==0),
//   exactly matching the reference's pad-then-window semantics.
// =====================================================================
__global__ __launch_bounds__(256) void attn_kernel(const float* __restrict__ pos_bias,
                                                   float* __restrict__ out) {
    extern __shared__ float sm[];
    float* Qs = sm;                       // [64][32]          2048 f
    float* Kt = sm + 2048;                // [32][225] (K->V)  7200 f
    float* Ps = sm + 2048 + 7200;         // [64][224]        14336 f

    const int nb = blockIdx.x, h = blockIdx.y, b = blockIdx.z;
    const int by = nb >> 3, bx = nb & 7;
    const int tid = threadIdx.x;
    const int w = tid >> 5, lane = tid & 31;
    const float* qkv_b = g_qkv + (size_t)b * NPIX * QKVW;

    // ---- load Q tile [64 rows][32] ----
    #pragma unroll
    for (int it = 0; it < 2; ++it) {
        int idx = tid + it * 256;                 // 0..511 float4 slots
        int r = idx >> 3, d4 = (idx & 7) << 2;
        int py = by * BSZ + (r >> 3), px = bx * BSZ + (r & 7);
        *(float4*)(Qs + r * 32 + d4) =
            *(const float4*)(qkv_b + (py * 64 + px) * QKVW + h * DHQK + d4);
    }
    // ---- gather K (transposed, zero-padded halo) ----
    for (int idx = tid; idx < WIN2 * 32; idx += 256) {
        int kk = idx >> 5, d = idx & 31;
        int wy = kk / WIN, wx = kk - wy * WIN;
        int py = by * BSZ - HALO + wy, px = bx * BSZ - HALO + wx;
        float v = 0.f;
        if ((unsigned)py < 64u && (unsigned)px < 64u)
            v = qkv_b[(py * 64 + px) * QKVW + 256 + h * 64 + d];
        Kt[d * 225 + kk] = v;
    }
    __syncthreads();

    // ---- scores: S[8 rows][7 col-chunks] in registers ----
    float s[8][7];
    #pragma unroll
    for (int mi = 0; mi < 8; ++mi)
        #pragma unroll
        for (int nc = 0; nc < 7; ++nc) s[mi][nc] = 0.f;

    const float* qrow = Qs + (w * 8) * 32;
    #pragma unroll 4
    for (int d = 0; d < 32; ++d) {
        float kv[7];
        #pragma unroll
        for (int nc = 0; nc < 7; ++nc) kv[nc] = Kt[d * 225 + nc * 32 + lane];
        #pragma unroll
        for (int mi = 0; mi < 8; ++mi) {
            float qd = qrow[mi * 32 + d];
            #pragma unroll
            for (int nc = 0; nc < 7; ++nc) s[mi][nc] = fmaf(qd, kv[nc], s[mi][nc]);
        }
    }

    // ---- bias + mask + softmax, write P rows to smem ----
    const float* pb = pos_bias + (size_t)(h * 64 + w * 8) * WIN2;
    const float NEG = -1e30f;
    #pragma unroll
    for (int mi = 0; mi < 8; ++mi) {
        #pragma unroll
        for (int nc = 0; nc < 7; ++nc) {
            int kk = nc * 32 + lane;
            s[mi][nc] = (kk < WIN2) ? fmaf(s[mi][nc], SCALE_QK, pb[mi * WIN2 + kk]) : NEG;
        }
        float mx = s[mi][0];
        #pragma unroll
        for (int nc = 1; nc < 7; ++nc) mx = fmaxf(mx, s[mi][nc]);
        #pragma unroll
        for (int off = 16; off > 0; off >>= 1)
            mx = fmaxf(mx, __shfl_xor_sync(0xffffffffu, mx, off));
        float sum = 0.f;
        #pragma unroll
        for (int nc = 0; nc < 7; ++nc) {
            float e = __expf(s[mi][nc] - mx);
            s[mi][nc] = e;
            sum += e;
        }
        #pragma unroll
        for (int off = 16; off > 0; off >>= 1)
            sum += __shfl_xor_sync(0xffffffffu, sum, off);
        float inv = 1.f / sum;
        #pragma unroll
        for (int nc = 0; nc < 7; ++nc)
            Ps[(w * 8 + mi) * NPAD + nc * 32 + lane] = s[mi][nc] * inv;
    }
    __syncthreads();   // all warps done reading Kt

    // ---- gather V into the K buffer ----
    for (int idx = tid; idx < WIN2 * 32; idx += 256) {
        int kk = idx >> 5, d = idx & 31;
        int wy = kk / WIN, wx = kk - wy * WIN;
        int py = by * BSZ - HALO + wy, px = bx * BSZ - HALO + wx;
        float v = 0.f;
        if ((unsigned)py < 64u && (unsigned)px < 64u)
            v = qkv_b[(py * 64 + px) * QKVW + 256 + h * 64 + 32 + d];
        Kt[d * 225 + kk] = v;
    }
    __syncthreads();

    // ---- PV: lane == output dim d; P rows broadcast as float4 ----
    float acc[8];
    #pragma unroll
    for (int mi = 0; mi < 8; ++mi) acc[mi] = 0.f;
    const float* vrow = Kt + lane * 225;
    const float* prow = Ps + (w * 8) * NPAD;
    for (int n4 = 0; n4 < WIN2 / 4; ++n4) {
        float v0 = vrow[n4 * 4 + 0];
        float v1 = vrow[n4 * 4 + 1];
        float v2 = vrow[n4 * 4 + 2];
        float v3 = vrow[n4 * 4 + 3];
        #pragma unroll
        for (int mi = 0; mi < 8; ++mi) {
            float4 p = *(const float4*)(prow + mi * NPAD + n4 * 4);
            acc[mi] = fmaf(p.x, v0, acc[mi]);
            acc[mi] = fmaf(p.y, v1, acc[mi]);
            acc[mi] = fmaf(p.z, v2, acc[mi]);
            acc[mi] = fmaf(p.w, v3, acc[mi]);
        }
    }

    // ---- stage output in smem (reuse Q region), then 32B-sector stores ----
    #pragma unroll
    for (int mi = 0; mi < 8; ++mi)
        Qs[(w * 8 + mi) * 32 + lane] = acc[mi];
    __syncthreads();

    const int d = tid >> 3, qy = tid & 7;   // one (channel, image-row) per thread
    float v0 = Qs[(qy * 8 + 0) * 32 + d], v1 = Qs[(qy * 8 + 1) * 32 + d];
    float v2 = Qs[(qy * 8 + 2) * 32 + d], v3 = Qs[(qy * 8 + 3) * 32 + d];
    float v4 = Qs[(qy * 8 + 4) * 32 + d], v5 = Qs[(qy * 8 + 5) * 32 + d];
    float v6 = Qs[(qy * 8 + 6) * 32 + d], v7 = Qs[(qy * 8 + 7) * 32 + d];
    float* op = out + ((size_t)((b * HEADS + h) * DHV + d) * 64 + by * BSZ + qy) * 64
                    + bx * BSZ;
    *(float4*)(op)     = make_float4(v0, v1, v2, v3);
    *(float4*)(op + 4) = make_float4(v4, v5, v6, v7);
}

// =====================================================================
extern "C" void kernel_launch(void* const* d_in, const int* in_sizes, int n_in,
                              void* d_out, int out_size) {
    const float* x   = (const float*)d_in[0];
    const float* Wq  = (const float*)d_in[1];
    const float* Wkv = (const float*)d_in[2];
    const float* pb  = (const float*)d_in[3];
    float* out = (float*)d_out;

    // 1) fused QKV projection: grid (n-tiles=6, m-tiles=512) so the 6 n-tiles
    //    sharing an x tile are adjacent in schedule (x stays L2-hot).
    qkv_gemm<<<dim3(6, 512), 256>>>(x, Wq, Wkv);

    // 2) halo attention, 94,336 B dynamic smem per block (2 blocks/SM fit).
    const int smem_bytes = (2048 + 7200 + 64 * NPAD) * 4;
    cudaFuncSetAttribute(attn_kernel,
                         cudaFuncAttributeMaxDynamicSharedMemorySize, smem_bytes);
    attn_kernel<<<dim3(64, HEADS, NBATCH), 256, smem_bytes>>>(pb, out);
}